// round 17
// baseline (speedup 1.0000x reference)
#include <cuda_runtime.h>
#include <cuda_bf16.h>

#define NNODES 50000
#define FIN    128
#define DDIM   64
#define HDIM   128
#define BGRAPH 16
#define E1N    800000
#define E2N    200000
#define AREG   2000
#define NREG   (BGRAPH * AREG)   // 32000
#define SLOTS  2048
#define NSLOTS (BGRAPH * SLOTS)  // 32768
#define BMWORDS 1568
#define DEGCAP 96
#define DEGCAP2 64

typedef unsigned long long ull;
typedef unsigned int u32;

// ---------------- helpers -------------------------------------------------------
__device__ __forceinline__ u32 bf2_hi(float a, float b) {
    __nv_bfloat162 h = __floats2bfloat162_rn(a, b);
    return *reinterpret_cast<u32*>(&h);
}
__device__ __forceinline__ u32 bf2_lo(float a, float b) {
    float ra = a - __bfloat162float(__float2bfloat16(a));
    float rb = b - __bfloat162float(__float2bfloat16(b));
    __nv_bfloat162 l = __floats2bfloat162_rn(ra, rb);
    return *reinterpret_cast<u32*>(&l);
}
__device__ __forceinline__ void mma16816(float* c, u32 a0, u32 a1, u32 a2, u32 a3,
                                         u32 b0, u32 b1) {
    asm("mma.sync.aligned.m16n8k16.row.col.f32.bf16.bf16.f32 "
        "{%0,%1,%2,%3}, {%4,%5,%6,%7}, {%8,%9}, {%0,%1,%2,%3};"
        : "+f"(c[0]), "+f"(c[1]), "+f"(c[2]), "+f"(c[3])
        : "r"(a0), "r"(a1), "r"(a2), "r"(a3), "r"(b0), "r"(b1));
}
__device__ __forceinline__ u32 smem_u32(const void* p) {
    u32 a;
    asm("{ .reg .u64 t; cvta.to.shared.u64 t, %1; cvt.u32.u64 %0, t; }"
        : "=r"(a) : "l"(p));
    return a;
}
__device__ __forceinline__ void cpa16(u32 smem_addr, const void* gptr) {
    asm volatile("cp.async.cg.shared.global [%0], [%1], 16;"
                 :: "r"(smem_addr), "l"(gptr) : "memory");
}
__device__ __forceinline__ void cpa16z(u32 smem_addr, const void* gptr, u32 sz) {
    asm volatile("cp.async.cg.shared.global [%0], [%1], 16, %2;"
                 :: "r"(smem_addr), "l"(gptr), "r"(sz) : "memory");
}
#define CP_COMMIT() asm volatile("cp.async.commit_group;" ::: "memory")
#define CP_WAIT0()  asm volatile("cp.async.wait_group 0;" ::: "memory")

__host__ __device__ __forceinline__ int pp_of(int jg) {
    return ((jg >> 2) & 1) + (jg & 3) * 2 + (jg >> 3) * 8;
}

// ---------------- scratch -------------------------------------------------------
__device__ __align__(16) float d_yl[NNODES * DDIM];
__device__ __align__(16) float d_yr[NNODES * DDIM];
__device__ __align__(16) float d_h1[NNODES * DDIM];
__device__ __align__(16) int   d_cnt[NNODES];
__device__ __align__(16) int   d_csr[NNODES * DEGCAP];
__device__ __align__(16) float d_gl[NNODES * DDIM];
__device__ __align__(16) float d_gr[NNODES * DDIM];
__device__ __align__(16) int   d_slotmap[BGRAPH * NNODES];
__device__ __align__(16) unsigned d_bitmap[BGRAPH * BMWORDS];
__device__ __align__(16) int   d_counter[BGRAPH];
__device__ __align__(16) int   d_cnt2[NSLOTS];
__device__ __align__(16) int   d_csr2[NSLOTS * DEGCAP2];
__device__ __align__(16) float d_acc2[NSLOTS * DDIM];
__device__ __align__(16) float d_deg2[NSLOTS];
__device__ __align__(16) float d_u[BGRAPH * HDIM];
__device__ __align__(16) float d_c[BGRAPH];
// preconverted weights (pair-permuted bf16 split; chunk-major [c][n][24])
__device__ __align__(16) u32 d_B1h[4 * 128 * 24];
__device__ __align__(16) u32 d_B1l[4 * 128 * 24];
__device__ __align__(16) u32 d_B2h[2 * 128 * 24];
__device__ __align__(16) u32 d_B2l[2 * 128 * 24];
__device__ __align__(16) u32 d_Wmh[2 * 128 * 24];
__device__ __align__(16) u32 d_Wml[2 * 128 * 24];

// ---------------- init kernel: clears + weight preconversion --------------------
static constexpr int CLR_SMAP = BGRAPH * NNODES / 4;
static constexpr int CLR_BMAP = BGRAPH * BMWORDS / 4;
static constexpr int CLR_CNT  = BGRAPH / 4;
static constexpr int CLR_CNT1 = NNODES / 4;
static constexpr int CLR_CNT2 = NSLOTS / 4;
static constexpr int INIT_W   = 1024;
static constexpr int INIT_TOTAL = CLR_SMAP + CLR_BMAP + CLR_CNT + CLR_CNT1 +
                                  CLR_CNT2 + INIT_W;

__global__ void init_kernel(const float* __restrict__ W1l,
                            const float* __restrict__ W1r,
                            const float* __restrict__ W2l,
                            const float* __restrict__ W2r,
                            const float* __restrict__ Wm) {
    int i = blockIdx.x * blockDim.x + threadIdx.x;
    if (i < CLR_SMAP) { ((int4*)d_slotmap)[i] = make_int4(-1, -1, -1, -1); return; }
    i -= CLR_SMAP;
    if (i < CLR_BMAP) { ((uint4*)d_bitmap)[i] = make_uint4(0, 0, 0, 0); return; }
    i -= CLR_BMAP;
    if (i < CLR_CNT)  { ((int4*)d_counter)[i] = make_int4(0, 0, 0, 0); return; }
    i -= CLR_CNT;
    if (i < CLR_CNT1) { ((int4*)d_cnt)[i] = make_int4(0, 0, 0, 0); return; }
    i -= CLR_CNT1;
    if (i < CLR_CNT2) { ((int4*)d_cnt2)[i] = make_int4(0, 0, 0, 0); return; }
    i -= CLR_CNT2;
    if (i >= INIT_W) return;
    if (i < 512) {
        int c = i >> 7, n = i & 127;
        const float* W = (n < 64) ? W1l : W1r;
        int nc = n & 63;
        u32* oh = d_B1h + (c * 128 + n) * 24;
        u32* ol = d_B1l + (c * 128 + n) * 24;
#pragma unroll
        for (int jg = 0; jg < 16; jg++) {
            int k = c * 32 + 2 * jg;
            float wx = W[k * 64 + nc];
            float wy = W[(k + 1) * 64 + nc];
            int pp = pp_of(jg);
            oh[pp] = bf2_hi(wx, wy);
            ol[pp] = bf2_lo(wx, wy);
        }
    } else if (i < 768) {
        int id = i - 512;
        int c = id >> 7, n = id & 127;
        const float* W = (n < 64) ? W2l : W2r;
        int nc = n & 63;
        u32* oh = d_B2h + (c * 128 + n) * 24;
        u32* ol = d_B2l + (c * 128 + n) * 24;
#pragma unroll
        for (int jg = 0; jg < 16; jg++) {
            int k = c * 32 + 2 * jg;
            float wx = W[k * 64 + nc];
            float wy = W[(k + 1) * 64 + nc];
            int pp = pp_of(jg);
            oh[pp] = bf2_hi(wx, wy);
            ol[pp] = bf2_lo(wx, wy);
        }
    } else {
        int id = i - 768;
        int c = id >> 7, n = id & 127;
        u32* oh = d_Wmh + (c * 128 + n) * 24;
        u32* ol = d_Wml + (c * 128 + n) * 24;
#pragma unroll
        for (int jg = 0; jg < 16; jg++) {
            int k = c * 32 + 2 * jg;
            float wx = Wm[k * 128 + n];
            float wy = Wm[(k + 1) * 128 + n];
            int pp = pp_of(jg);
            oh[pp] = bf2_hi(wx, wy);
            ol[pp] = bf2_lo(wx, wy);
        }
    }
}

// ---------------- conv1 bucket fill ---------------------------------------------
__global__ void fill_kernel(const int* __restrict__ ei) {
    int idx = (blockIdx.x * blockDim.x + threadIdx.x) * 4;
    if (idx >= E1N) return;
    int4 s = *(const int4*)(ei + idx);
    int4 d = *(const int4*)(ei + E1N + idx);
    int o0 = atomicAdd(&d_cnt[d.x], 1);
    int o1 = atomicAdd(&d_cnt[d.y], 1);
    int o2 = atomicAdd(&d_cnt[d.z], 1);
    int o3 = atomicAdd(&d_cnt[d.w], 1);
    d_csr[d.x * DEGCAP + o0] = s.x;
    d_csr[d.y * DEGCAP + o1] = s.y;
    d_csr[d.z * DEGCAP + o2] = s.z;
    d_csr[d.w * DEGCAP + o3] = s.w;
}

// ---------------- conv1 gather: index-batched -----------------------------------
__global__ void gather1_kernel() {
    int tid = blockIdx.x * blockDim.x + threadIdx.x;
    int w = tid >> 5, lane = tid & 31;
    int node = 2 * w + (lane >> 4);
    int j = lane & 15;
    int deg = d_cnt[node];
    const int4* csr4 = (const int4*)(d_csr + node * DEGCAP);
    float4 acc = make_float4(0.f, 0.f, 0.f, 0.f);
    for (int i0 = 0; i0 < deg; i0 += 16) {
        int q = i0 >> 2;
        int4 a = csr4[q], b = csr4[q + 1], c = csr4[q + 2], d4 = csr4[q + 3];
        int idx[16] = {a.x, a.y, a.z, a.w, b.x, b.y, b.z, b.w,
                       c.x, c.y, c.z, c.w, d4.x, d4.y, d4.z, d4.w};
#pragma unroll
        for (int u = 0; u < 16; u++) {
            if (i0 + u < deg) {
                float4 v = ((const float4*)(d_yl + idx[u] * 64))[j];
                acc.x += v.x; acc.y += v.y; acc.z += v.z; acc.w += v.w;
            }
        }
    }
    float inv = 1.f / fmaxf((float)deg, 1.f);
    float4 y = ((const float4*)(d_yr + node * 64))[j];
    float4 h;
    h.x = fmaxf(acc.x * inv + y.x, 0.f);
    h.y = fmaxf(acc.y * inv + y.y, 0.f);
    h.z = fmaxf(acc.z * inv + y.z, 0.f);
    h.w = fmaxf(acc.w * inv + y.w, 0.f);
    ((float4*)(d_h1 + node * 64))[j] = h;
}

// ================= GEMM1: D[128,128] = x @ [W1l|W1r], cp.async 2-buffer =========
__global__ __launch_bounds__(256) void mma_gemm1(const float* __restrict__ X,
                                                 const u32* __restrict__ Bgh,
                                                 const u32* __restrict__ Bgl,
                                                 const float* __restrict__ bias,
                                                 float* __restrict__ C1,
                                                 float* __restrict__ C2,
                                                 int nrows) {
    extern __shared__ u32 sm[];
    const int t = threadIdx.x;
    const int w = t >> 5, lane = t & 31;
    const int g = lane >> 2, tg = lane & 3;
    const int row0 = blockIdx.x * 128;

    float acc[16][4];
#pragma unroll
    for (int nt = 0; nt < 16; nt++)
#pragma unroll
        for (int i = 0; i < 4; i++) acc[nt][i] = 0.f;

    auto copy_chunk = [&](int c, int buf) {
        u32 sbase = smem_u32(sm + buf * 10752);
#pragma unroll
        for (int i = 0; i < 4; i++) {
            int idx = t + i * 256;
            int row = idx >> 3, gc = idx & 7;
            int grow = row0 + row;
            u32 sz = (grow < nrows) ? 16u : 0u;
            const float* src = X + (long)min(grow, nrows - 1) * 128 + c * 32 + gc * 4;
            cpa16z(sbase + (row * 36 + gc * 4) * 4, src, sz);
        }
#pragma unroll
        for (int i = 0; i < 3; i++) {
            int idx = t + i * 256;
            cpa16(sbase + 4608 * 4 + idx * 16, Bgh + c * 3072 + idx * 4);
            cpa16(sbase + 7680 * 4 + idx * 16, Bgl + c * 3072 + idx * 4);
        }
        CP_COMMIT();
    };

    copy_chunk(0, 0);

#pragma unroll
    for (int c = 0; c < 4; c++) {
        CP_WAIT0();
        __syncthreads();
        if (c + 1 < 4) copy_chunk(c + 1, (c + 1) & 1);

        const float* sAf = (const float*)(sm + (c & 1) * 10752);
        const __nv_bfloat16* sBh = (const __nv_bfloat16*)(sm + (c & 1) * 10752 + 4608);
        const __nv_bfloat16* sBl = (const __nv_bfloat16*)(sm + (c & 1) * 10752 + 7680);

#pragma unroll
        for (int ks = 0; ks < 2; ks++) {
            const float* Ar0 = sAf + (w * 16 + g) * 36 + ks * 16 + 2 * tg;
            const float* Ar1 = Ar0 + 8 * 36;
            float2 p00 = *(const float2*)Ar0;
            float2 p02 = *(const float2*)(Ar0 + 8);
            float2 p10 = *(const float2*)Ar1;
            float2 p12 = *(const float2*)(Ar1 + 8);
            u32 h0 = bf2_hi(p00.x, p00.y), h2 = bf2_hi(p02.x, p02.y);
            u32 h1 = bf2_hi(p10.x, p10.y), h3 = bf2_hi(p12.x, p12.y);
            u32 l0 = bf2_lo(p00.x, p00.y), l2 = bf2_lo(p02.x, p02.y);
            u32 l1 = bf2_lo(p10.x, p10.y), l3 = bf2_lo(p12.x, p12.y);
#pragma unroll
            for (int nt = 0; nt < 16; nt++) {
                ull bh = *(const ull*)(sBh + (nt * 8 + g) * 48 + ks * 16 + tg * 4);
                u32 bh0 = (u32)bh, bh1 = (u32)(bh >> 32);
                mma16816(acc[nt], h0, h1, h2, h3, bh0, bh1);
                mma16816(acc[nt], l0, l1, l2, l3, bh0, bh1);
                ull bl = *(const ull*)(sBl + (nt * 8 + g) * 48 + ks * 16 + tg * 4);
                mma16816(acc[nt], h0, h1, h2, h3, (u32)bl, (u32)(bl >> 32));
            }
        }
        __syncthreads();
    }

    int r0 = row0 + w * 16 + g;
#pragma unroll
    for (int nt = 0; nt < 16; nt++) {
        int col = nt * 8 + tg * 2;
        if (col < 64) {
            if (r0 < nrows)
                *(float2*)(C1 + (long)r0 * 64 + col) = make_float2(acc[nt][0], acc[nt][1]);
            if (r0 + 8 < nrows)
                *(float2*)(C1 + (long)(r0 + 8) * 64 + col) = make_float2(acc[nt][2], acc[nt][3]);
        } else {
            int c2 = col - 64;
            float2 bb = *(const float2*)(bias + c2);
            if (r0 < nrows)
                *(float2*)(C2 + (long)r0 * 64 + c2) =
                    make_float2(acc[nt][0] + bb.x, acc[nt][1] + bb.y);
            if (r0 + 8 < nrows)
                *(float2*)(C2 + (long)(r0 + 8) * 64 + c2) =
                    make_float2(acc[nt][2] + bb.x, acc[nt][3] + bb.y);
        }
    }
}

// ================= GEMM2: D = h1 @ [W2l|W2r], single upfront load ===============
__global__ __launch_bounds__(256) void mma_gemm2(const u32* __restrict__ Bgh,
                                                 const u32* __restrict__ Bgl,
                                                 const float* __restrict__ bias,
                                                 float* __restrict__ C1,
                                                 float* __restrict__ C2,
                                                 int nrows) {
    extern __shared__ u32 sm[];
    const int t = threadIdx.x;
    const int w = t >> 5, lane = t & 31;
    const int g = lane >> 2, tg = lane & 3;
    const int row0 = blockIdx.x * 128;

    {
        u32 sh = smem_u32(sm);
#pragma unroll
        for (int i = 0; i < 8; i++) {
            int idx = t + i * 256;
            int row = idx >> 4, gc = idx & 15;
            int grow = row0 + row;
            u32 sz = (grow < nrows) ? 16u : 0u;
            cpa16z(sh + (row * 68 + gc * 4) * 4,
                   d_h1 + (long)min(grow, nrows - 1) * 64 + gc * 4, sz);
        }
        u32 sb = smem_u32(sm + 8704);
#pragma unroll
        for (int i = 0; i < 6; i++) {
            int idx = t + i * 256;
            cpa16(sb + idx * 16, Bgh + idx * 4);
            cpa16(sb + 6144 * 4 + idx * 16, Bgl + idx * 4);
        }
        CP_COMMIT();
        CP_WAIT0();
        __syncthreads();
    }

    float acc[16][4];
#pragma unroll
    for (int nt = 0; nt < 16; nt++)
#pragma unroll
        for (int i = 0; i < 4; i++) acc[nt][i] = 0.f;

    const float* sH = (const float*)sm;

#pragma unroll
    for (int c = 0; c < 2; c++) {
        const __nv_bfloat16* sBh = (const __nv_bfloat16*)(sm + 8704 + c * 3072);
        const __nv_bfloat16* sBl = (const __nv_bfloat16*)(sm + 14848 + c * 3072);
#pragma unroll
        for (int ks = 0; ks < 2; ks++) {
            const float* Ar0 = sH + (w * 16 + g) * 68 + c * 32 + ks * 16 + 2 * tg;
            const float* Ar1 = Ar0 + 8 * 68;
            float2 p00 = *(const float2*)Ar0;
            float2 p02 = *(const float2*)(Ar0 + 8);
            float2 p10 = *(const float2*)Ar1;
            float2 p12 = *(const float2*)(Ar1 + 8);
            u32 h0 = bf2_hi(p00.x, p00.y), h2 = bf2_hi(p02.x, p02.y);
            u32 h1 = bf2_hi(p10.x, p10.y), h3 = bf2_hi(p12.x, p12.y);
            u32 l0 = bf2_lo(p00.x, p00.y), l2 = bf2_lo(p02.x, p02.y);
            u32 l1 = bf2_lo(p10.x, p10.y), l3 = bf2_lo(p12.x, p12.y);
#pragma unroll
            for (int nt = 0; nt < 16; nt++) {
                ull bh = *(const ull*)(sBh + (nt * 8 + g) * 48 + ks * 16 + tg * 4);
                u32 bh0 = (u32)bh, bh1 = (u32)(bh >> 32);
                mma16816(acc[nt], h0, h1, h2, h3, bh0, bh1);
                mma16816(acc[nt], l0, l1, l2, l3, bh0, bh1);
                ull bl = *(const ull*)(sBl + (nt * 8 + g) * 48 + ks * 16 + tg * 4);
                mma16816(acc[nt], h0, h1, h2, h3, (u32)bl, (u32)(bl >> 32));
            }
        }
    }

    int r0 = row0 + w * 16 + g;
#pragma unroll
    for (int nt = 0; nt < 16; nt++) {
        int col = nt * 8 + tg * 2;
        if (col < 64) {
            if (r0 < nrows)
                *(float2*)(C1 + (long)r0 * 64 + col) = make_float2(acc[nt][0], acc[nt][1]);
            if (r0 + 8 < nrows)
                *(float2*)(C1 + (long)(r0 + 8) * 64 + col) = make_float2(acc[nt][2], acc[nt][3]);
        } else {
            int c2 = col - 64;
            float2 bb = *(const float2*)(bias + c2);
            if (r0 < nrows)
                *(float2*)(C2 + (long)r0 * 64 + c2) =
                    make_float2(acc[nt][0] + bb.x, acc[nt][1] + bb.y);
            if (r0 + 8 < nrows)
                *(float2*)(C2 + (long)(r0 + 8) * 64 + c2) =
                    make_float2(acc[nt][2] + bb.x, acc[nt][3] + bb.y);
        }
    }
}

// ---------------- slot assignment + bitmap --------------------------------------
__global__ void slot_kernel(const int* __restrict__ targets,
                            const int* __restrict__ regions) {
    int idx = blockIdx.x * blockDim.x + threadIdx.x;
    if (idx >= BGRAPH * (AREG + 1)) return;
    int b = idx / (AREG + 1);
    int j = idx % (AREG + 1);
    int node = (j == AREG) ? targets[b] : regions[b * AREG + j];
    atomicOr(&d_bitmap[b * BMWORDS + (node >> 5)], 1u << (node & 31));
    int* p = &d_slotmap[b * NNODES + node];
    if (atomicCAS(p, -1, -2) == -1) {
        int s = atomicAdd(&d_counter[b], 1);
        atomicExch(p, s);
    }
}

// ---------------- conv2 bucket fill (bitmap-filtered) ---------------------------
__global__ void fill2_kernel(const int* __restrict__ ne) {
    __shared__ unsigned sbm[BMWORDS];
    const int b = blockIdx.y;
    for (int i = threadIdx.x; i < BMWORDS; i += 320)
        sbm[i] = d_bitmap[b * BMWORDS + i];
    __syncthreads();

    const long base = (long)b * 2 * E2N;
    int e0 = blockIdx.x * 1600 + threadIdx.x;
#pragma unroll
    for (int it = 0; it < 5; it++) {
        int e = e0 + it * 320;
        int dst = ne[base + E2N + e];
        if ((sbm[dst >> 5] >> (dst & 31)) & 1u) {
            int slot = d_slotmap[b * NNODES + dst];
            int src = ne[base + e];
            int gs = b * SLOTS + slot;
            int o = atomicAdd(&d_cnt2[gs], 1);
            d_csr2[(gs << 6) + o] = src;
        }
    }
}

// ---------------- conv2 gather: acc2[slot] = sum gl[src], deg2 = cnt ------------
__global__ void gather2_kernel() {
    int tid = blockIdx.x * blockDim.x + threadIdx.x;
    int w = tid >> 5, lane = tid & 31;
    int sl = 2 * w + (lane >> 4);
    int j = lane & 15;
    int deg = d_cnt2[sl];
    const int4* csr4 = (const int4*)(d_csr2 + (sl << 6));
    float4 acc = make_float4(0.f, 0.f, 0.f, 0.f);
    for (int i0 = 0; i0 < deg; i0 += 16) {
        int q = i0 >> 2;
        int4 a = csr4[q], b = csr4[q + 1], c = csr4[q + 2], d4 = csr4[q + 3];
        int idx[16] = {a.x, a.y, a.z, a.w, b.x, b.y, b.z, b.w,
                       c.x, c.y, c.z, c.w, d4.x, d4.y, d4.z, d4.w};
#pragma unroll
        for (int u = 0; u < 16; u++) {
            if (i0 + u < deg) {
                float4 v = ((const float4*)(d_gl + idx[u] * 64))[j];
                acc.x += v.x; acc.y += v.y; acc.z += v.z; acc.w += v.w;
            }
        }
    }
    ((float4*)(d_acc2 + sl * 64))[j] = acc;
    if (j == 0) d_deg2[sl] = (float)deg;   // FIX: per half-warp (lanes 0 AND 16)
}

// ---------------- u_b = Wo @ t_b , c_b = bo . t_b -------------------------------
__global__ void u_kernel(const int* __restrict__ targets,
                         const float* __restrict__ Wo,
                         const float* __restrict__ bo) {
    int idx = blockIdx.x * blockDim.x + threadIdx.x;
    if (idx >= BGRAPH * HDIM) return;
    int b = idx >> 7;
    int h = idx & 127;
    int node = targets[b];
    int s = d_slotmap[b * NNODES + node];
    int base = (b * SLOTS + s) * 64;
    float inv = 1.f / fmaxf(d_deg2[b * SLOTS + s], 1.f);
    float acc = 0.f, c = 0.f;
#pragma unroll
    for (int d = 0; d < 64; d++) {
        float td = fmaxf(d_acc2[base + d] * inv + d_gr[node * 64 + d], 0.f);
        acc += Wo[h * 64 + d] * td;
        c += bo[d] * td;
    }
    d_u[idx] = acc;
    if (h == 0) d_c[b] = c;
}

// ================= final readout as HMMA GEMM (h2 computed in loader) ===========
__global__ __launch_bounds__(256) void final_mma(const int* __restrict__ regions,
                                                 const float* __restrict__ bm,
                                                 float* __restrict__ q) {
    extern __shared__ u32 sm[];
    const int t = threadIdx.x;
    const int w = t >> 5, lane = t & 31;
    const int g = lane >> 2, tg = lane & 3;
    const int row0 = blockIdx.x * 128;

    {
        u32 sb = smem_u32(sm + 8704);
#pragma unroll
        for (int i = 0; i < 6; i++) {
            int idx = t + i * 256;
            cpa16(sb + idx * 16, d_Wmh + idx * 4);
            cpa16(sb + 6144 * 4 + idx * 16, d_Wml + idx * 4);
        }
        u32 su = smem_u32(sm + 20992);
#pragma unroll
        for (int i = 0; i < 2; i++) {
            int idx = t + i * 256;
            cpa16(su + idx * 16, d_u + idx * 4);
        }
        if (t < 32) cpa16(smem_u32(sm + 23040) + t * 16, bm + t * 4);
        if (t < 4)  cpa16(smem_u32(sm + 23168) + t * 16, d_c + t * 4);
        CP_COMMIT();
    }

    {
        int row = t >> 1, half = t & 1;
        int p = row0 + row;
        int b = p / AREG;
        int node = regions[p];
        int s = d_slotmap[b * NNODES + node];
        int base = (b * SLOTS + s) * 64 + half * 32;
        float inv = 1.f / fmaxf(d_deg2[b * SLOTS + s], 1.f);
        const float4* ap = (const float4*)(d_acc2 + base);
        const float4* gp = (const float4*)(d_gr + node * 64 + half * 32);
        float4* dst = (float4*)((float*)sm + row * 68 + half * 32);
#pragma unroll
        for (int i = 0; i < 8; i++) {
            float4 a = ap[i];
            float4 g4 = gp[i];
            float4 h;
            h.x = fmaxf(a.x * inv + g4.x, 0.f);
            h.y = fmaxf(a.y * inv + g4.y, 0.f);
            h.z = fmaxf(a.z * inv + g4.z, 0.f);
            h.w = fmaxf(a.w * inv + g4.w, 0.f);
            dst[i] = h;
        }
    }
    CP_WAIT0();
    __syncthreads();

    float acc[16][4];
#pragma unroll
    for (int nt = 0; nt < 16; nt++)
#pragma unroll
        for (int i = 0; i < 4; i++) acc[nt][i] = 0.f;

    const float* sH = (const float*)sm;

#pragma unroll
    for (int c = 0; c < 2; c++) {
        const __nv_bfloat16* sBh = (const __nv_bfloat16*)(sm + 8704 + c * 3072);
        const __nv_bfloat16* sBl = (const __nv_bfloat16*)(sm + 14848 + c * 3072);
#pragma unroll
        for (int ks = 0; ks < 2; ks++) {
            const float* Ar0 = sH + (w * 16 + g) * 68 + c * 32 + ks * 16 + 2 * tg;
            const float* Ar1 = Ar0 + 8 * 68;
            float2 p00 = *(const float2*)Ar0;
            float2 p02 = *(const float2*)(Ar0 + 8);
            float2 p10 = *(const float2*)Ar1;
            float2 p12 = *(const float2*)(Ar1 + 8);
            u32 h0 = bf2_hi(p00.x, p00.y), h2 = bf2_hi(p02.x, p02.y);
            u32 h1 = bf2_hi(p10.x, p10.y), h3 = bf2_hi(p12.x, p12.y);
            u32 l0 = bf2_lo(p00.x, p00.y), l2 = bf2_lo(p02.x, p02.y);
            u32 l1 = bf2_lo(p10.x, p10.y), l3 = bf2_lo(p12.x, p12.y);
#pragma unroll
            for (int nt = 0; nt < 16; nt++) {
                ull bh = *(const ull*)(sBh + (nt * 8 + g) * 48 + ks * 16 + tg * 4);
                u32 bh0 = (u32)bh, bh1 = (u32)(bh >> 32);
                mma16816(acc[nt], h0, h1, h2, h3, bh0, bh1);
                mma16816(acc[nt], l0, l1, l2, l3, bh0, bh1);
                ull bl = *(const ull*)(sBl + (nt * 8 + g) * 48 + ks * 16 + tg * 4);
                mma16816(acc[nt], h0, h1, h2, h3, (u32)bl, (u32)(bl >> 32));
            }
        }
    }

    const float* su = (const float*)(sm + 20992);
    const float* sbm = (const float*)(sm + 23040);
    const float* sc = (const float*)(sm + 23168);
    int p0 = row0 + w * 16 + g;
    int p1 = p0 + 8;
    int b0 = p0 / AREG, b1 = p1 / AREG;
    const float* u0 = su + b0 * 128;
    const float* u1 = su + b1 * 128;
    float s0 = 0.f, s1 = 0.f;
#pragma unroll
    for (int nt = 0; nt < 16; nt++) {
        int col = nt * 8 + tg * 2;
        float bx = sbm[col], by = sbm[col + 1];
        s0 += fmaxf(acc[nt][0] + bx, 0.f) * u0[col]
            + fmaxf(acc[nt][1] + by, 0.f) * u0[col + 1];
        s1 += fmaxf(acc[nt][2] + bx, 0.f) * u1[col]
            + fmaxf(acc[nt][3] + by, 0.f) * u1[col + 1];
    }
    s0 += __shfl_xor_sync(0xffffffffu, s0, 1);
    s0 += __shfl_xor_sync(0xffffffffu, s0, 2);
    s1 += __shfl_xor_sync(0xffffffffu, s1, 1);
    s1 += __shfl_xor_sync(0xffffffffu, s1, 2);
    if (tg == 0) {
        q[p0] = s0 + sc[b0];
        q[p1] = s1 + sc[b1];
    }
}

// ---------------- launch ---------------------------------------------------------
extern "C" void kernel_launch(void* const* d_in, const int* in_sizes, int n_in,
                              void* d_out, int out_size) {
    const float* x       = (const float*)d_in[0];
    const int*   ei      = (const int*)  d_in[1];
    const int*   ne      = (const int*)  d_in[2];
    const int*   targets = (const int*)  d_in[3];
    const int*   regions = (const int*)  d_in[4];
    const float* W1l     = (const float*)d_in[5];
    const float* W1r     = (const float*)d_in[6];
    const float* b1      = (const float*)d_in[7];
    const float* W2l     = (const float*)d_in[8];
    const float* W2r     = (const float*)d_in[9];
    const float* b2      = (const float*)d_in[10];
    const float* Wm      = (const float*)d_in[11];
    const float* bm      = (const float*)d_in[12];
    const float* Wo      = (const float*)d_in[13];
    const float* bo      = (const float*)d_in[14];
    float* q = (float*)d_out;

    float *p_yl, *p_yr, *p_gl, *p_gr;
    u32 *p_B1h, *p_B1l, *p_B2h, *p_B2l;
    cudaGetSymbolAddress((void**)&p_yl, d_yl);
    cudaGetSymbolAddress((void**)&p_yr, d_yr);
    cudaGetSymbolAddress((void**)&p_gl, d_gl);
    cudaGetSymbolAddress((void**)&p_gr, d_gr);
    cudaGetSymbolAddress((void**)&p_B1h, d_B1h);
    cudaGetSymbolAddress((void**)&p_B1l, d_B1l);
    cudaGetSymbolAddress((void**)&p_B2h, d_B2h);
    cudaGetSymbolAddress((void**)&p_B2l, d_B2l);

    cudaFuncSetAttribute(mma_gemm1, cudaFuncAttributeMaxDynamicSharedMemorySize, 86016);
    cudaFuncSetAttribute(mma_gemm2, cudaFuncAttributeMaxDynamicSharedMemorySize, 83968);
    cudaFuncSetAttribute(final_mma, cudaFuncAttributeMaxDynamicSharedMemorySize, 92736);

    // 0. init: clears + weight preconversion
    init_kernel<<<(INIT_TOTAL + 255) / 256, 256>>>(W1l, W1r, W2l, W2r, Wm);

    // 1. GEMM1: yl = x@W1l ; yr = x@W1r + b1
    mma_gemm1<<<391, 256, 86016>>>(x, p_B1h, p_B1l, b1, p_yl, p_yr, NNODES);

    // 2. conv1 bucket fill
    fill_kernel<<<(E1N / 4 + 255) / 256, 256>>>(ei);

    // 3. conv1 gather -> h1    <-- profiled slot
    gather1_kernel<<<(NNODES / 2 * 32) / 256, 256>>>();

    // 4. GEMM2: gl = h1@W2l ; gr = h1@W2r + b2
    mma_gemm2<<<391, 256, 83968>>>(p_B2h, p_B2l, b2, p_gl, p_gr, NNODES);

    // 5. slot assignment + bitmap
    slot_kernel<<<(BGRAPH * (AREG + 1) + 255) / 256, 256>>>(targets, regions);

    // 6. conv2 bucket fill (bitmap-filtered)
    {
        dim3 grid(125, BGRAPH);
        fill2_kernel<<<grid, 320>>>(ne);
    }

    // 7. conv2 gather -> acc2, deg2
    gather2_kernel<<<(NSLOTS / 2 * 32) / 256, 256>>>();

    // 8. u_b = Wo @ t_b, c_b
    u_kernel<<<(BGRAPH * HDIM + 255) / 256, 256>>>(targets, Wo, bo);

    // 9. readout GEMM (h2 computed in loader)
    final_mma<<<NREG / 128, 256, 92736>>>(regions, bm, q);
}